// round 14
// baseline (speedup 1.0000x reference)
#include <cuda_runtime.h>
#include <cuda_bf16.h>

// QuantizedGRU: T=512, B=1024, H=12, Q7 fixed point (scale 128).
// Round 14 = Round 8 (best, 48.1us) with ONE scheduling change:
//   the fcnn epilogue's FMA work (qa/qb/qc/pa) stays in R8's position
//   (filler between v-values and gates), but its MIO ops (shfl_xor +
//   predicated STG) move to AFTER the STS->LDS broadcast, so the in-order
//   MIO queue is [STS, LDS x3, SHFL, STG] instead of [SHFL, STG, STS, LDS].
// All arithmetic identical to R8: exact x128 scaled-integer fp32 domain,
// every fused round a verified single-rounding (bit-exact).

#define TT  512
#define BB  1024
#define INV 0.0078125f
#define MAGIC 12582912.0f            /* 1.5 * 2^23 */
#define XROW 516                     /* padded x row: 512 + 4 OOB slots */

typedef unsigned long long u64;

__device__ __forceinline__ float rne(float v) {
    return __fadd_rn(__fadd_rn(v, MAGIC), -MAGIC);
}
__device__ __forceinline__ float rneq(float v) {
    return fminf(fmaxf(rne(v), -32768.0f), 32767.0f);
}
__device__ __forceinline__ float qs(float v) {   // quantized weight, scaled
    return rneq(__fmul_rn(v, 128.0f));
}
__device__ __forceinline__ float qr(float v) {   // quantized weight, real
    return __fmul_rn(qs(v), INV);
}
__device__ __forceinline__ u64 pk2(float lo, float hi) {
    u64 r;
    asm("mov.b64 %0, {%1, %2};" : "=l"(r) : "f"(lo), "f"(hi));
    return r;
}
__device__ __forceinline__ void fma2(u64& d, u64 a, u64 b) {
    asm("fma.rn.f32x2 %0, %1, %2, %0;" : "+l"(d) : "l"(a), "l"(b));
}
__device__ __forceinline__ u64 add2(u64 a, u64 b) {
    u64 r;
    asm("add.rn.f32x2 %0, %1, %2;" : "=l"(r) : "l"(a), "l"(b));
    return r;
}
__device__ __forceinline__ u64 mul2(u64 a, u64 b) {
    u64 r;
    asm("mul.rn.f32x2 %0, %1, %2;" : "=l"(r) : "l"(a), "l"(b));
    return r;
}
__device__ __forceinline__ void unpk2(float& lo, float& hi, u64 v) {
    asm("mov.b64 {%0, %1}, %2;" : "=f"(lo), "=f"(hi) : "l"(v));
}
__device__ __forceinline__ float hsum2(u64 v) {
    float lo, hi;
    unpk2(lo, hi, v);
    return __fadd_rn(lo, hi);
}
__device__ __forceinline__ unsigned smem_u32(const void* p) {
    unsigned a;
    asm("{ .reg .u64 t; cvta.to.shared.u64 t, %1; cvt.u32.u64 %0, t; }"
        : "=r"(a) : "l"(p));
    return a;
}

// ---------------------------------------------------------------------------
// 128 blocks x 128 threads: 8 batches/block, 16 threads/batch.
// lanes 0-11: gate triple r (W_hh rows r, r+12, r+24)
// lanes 12,13: FCNN rows (W1 rows 0-2 / 3-5), output pipelined 1 step behind
// lanes 14,15: zero weights (same instruction stream)
// ---------------------------------------------------------------------------
__global__ void __launch_bounds__(128, 1) gru_kernel(
        const float* __restrict__ x,
        const float* __restrict__ wih_raw, const float* __restrict__ whh_raw,
        const float* __restrict__ bih_raw, const float* __restrict__ bhh_raw,
        const float* __restrict__ w1_raw,  const float* __restrict__ b1_raw,
        const float* __restrict__ w2_raw,  const float* __restrict__ b2_raw,
        float* __restrict__ out) {
    __shared__ __align__(16) float xs[8 * XROW];       // [batch][t], padded
    __shared__ __align__(16) float hbuf[8 * 16];       // h broadcast rows

    const int tid = threadIdx.x;
    const int r   = tid & 15;
    const int bb  = tid >> 4;
    const int b0  = blockIdx.x << 3;
    const int b   = b0 + bb;

    // stage x transposed: xs[bj][t] = x[t][b0+bj]; zero the 4 pad slots
    for (int i = tid; i < TT * 8; i += 128) {
        const int t  = i >> 3;
        const int bj = i & 7;
        xs[bj * XROW + t] = x[t * BB + b0 + bj];
    }
    if (tid < 32) xs[(tid >> 2) * XROW + TT + (tid & 3)] = 0.0f;

    // ---- per-lane constants ----
    u64 wA[6], wB[6], wC[6];
    u64 ws01 = 0, cb01M = pk2(-MAGIC, -MAGIC);
    float ws2 = 0.f, cb2 = 0.f;
    float KC = __fmul_rn(-MAGIC, INV);
    float w2a = 0.f, w2b = 0.f, w2cS = 0.f;            // w2cS: SCALED weight
#pragma unroll
    for (int k = 0; k < 6; ++k) { wA[k] = 0; wB[k] = 0; wC[k] = 0; }

    if (r < 12) {
        const float* pA = whh_raw + r * 12;            // r-gate row
        const float* pB = whh_raw + (r + 12) * 12;     // z-gate row
        const float* pC = whh_raw + (r + 24) * 12;     // n-gate row
#pragma unroll
        for (int k = 0; k < 6; ++k) {
            wA[k] = pk2(qr(pA[2 * k]), qr(pA[2 * k + 1]));
            wB[k] = pk2(qr(pB[2 * k]), qr(pB[2 * k + 1]));
            wC[k] = pk2(qr(pC[2 * k]), qr(pC[2 * k + 1]));
        }
        ws01  = pk2(qs(wih_raw[r]), qs(wih_raw[r + 12]));
        cb01M = pk2((qs(bih_raw[r])      + qs(bhh_raw[r]))      - MAGIC,
                    (qs(bih_raw[r + 12]) + qs(bhh_raw[r + 12])) - MAGIC);
        ws2 = qs(wih_raw[r + 24]);
        cb2 = qs(bih_raw[r + 24]);
        KC  = __fmul_rn(qs(bhh_raw[r + 24]) - MAGIC, INV);
    } else if (r < 14) {
        const int r0 = (r - 12) * 3;
#pragma unroll
        for (int j = 0; j < 3; ++j) {
            const float* p = w1_raw + (r0 + j) * 12;
            u64* w = (j == 0) ? wA : ((j == 1) ? wB : wC);
#pragma unroll
            for (int k = 0; k < 6; ++k)
                w[k] = pk2(qr(p[2 * k]), qr(p[2 * k + 1]));
        }
        cb01M = pk2(qs(b1_raw[r0 + 0]) - MAGIC,
                    qs(b1_raw[r0 + 1]) - MAGIC);
        KC   = __fmul_rn(qs(b1_raw[r0 + 2]) - MAGIC, INV);
        w2a  = qr(w2_raw[r0 + 0]);
        w2b  = qr(w2_raw[r0 + 1]);
        w2cS = qs(w2_raw[r0 + 2]);   // scaled, since qCr is real-domain
    }
    const float b2sM = qs(b2_raw[0]) - MAGIC;
    const float K64  = 64.0f + 0.75f * MAGIC;   // exact
    const float MP   = MAGIC + 128.0f;
    const float MM   = MAGIC - 128.0f;
    const u64   M2   = pk2(MAGIC, MAGIC);

    __syncthreads();

    u64 hp[6];
#pragma unroll
    for (int k = 0; k < 6; ++k) hp[k] = 0;
    float hM_own = MAGIC;                       // h + MAGIC, h0 = 0
    float* op    = out + b - BB;                // output for step t-1

    const unsigned xsa = smem_u32(xs + bb * XROW);
    const unsigned hba = smem_u32(hbuf) + (bb << 6);
    const unsigned hst = hba + (r << 2);

    float4 xq = make_float4(0.f, 0.f, 0.f, 0.f);

#pragma unroll 4
    for (int t = 0; t <= TT; ++t) {
        if ((t & 3) == 0) {
            asm volatile("ld.shared.v4.f32 {%0,%1,%2,%3}, [%4];"
                : "=f"(xq.x), "=f"(xq.y), "=f"(xq.z), "=f"(xq.w)
                : "r"(xsa + (unsigned)t * 4u));
        }
        const float xcur = ((t & 3) == 0) ? xq.x :
                           ((t & 3) == 1) ? xq.y :
                           ((t & 3) == 2) ? xq.z : xq.w;

        // ii precompute (off critical path); packed for r/z, scalar for n.
        const u64 i01 = add2(add2(mul2(pk2(xcur, xcur), ws01), M2), cb01M);
        float i0, i1;
        unpk2(i0, i1, i01);                     // true ints
        const float i2M = __fadd_rn(__fadd_rn(__fmul_rn(xcur, ws2), MAGIC), cb2);

        // ---- packed dots with h_{t-1} (two 3-deep chains per row) ----
        u64 a0 = 0, a1 = 0, c0 = 0, c1 = 0, e0 = 0, e1 = 0;
        fma2(a0, hp[0], wA[0]); fma2(a0, hp[1], wA[1]); fma2(a0, hp[2], wA[2]);
        fma2(a1, hp[3], wA[3]); fma2(a1, hp[4], wA[4]); fma2(a1, hp[5], wA[5]);
        fma2(c0, hp[0], wC[0]); fma2(c0, hp[1], wC[1]); fma2(c0, hp[2], wC[2]);
        fma2(c1, hp[3], wC[3]); fma2(c1, hp[4], wC[4]); fma2(c1, hp[5], wC[5]);
        fma2(e0, hp[0], wB[0]); fma2(e0, hp[1], wB[1]); fma2(e0, hp[2], wB[2]);
        fma2(e1, hp[3], wB[3]); fma2(e1, hp[4], wB[4]); fma2(e1, hp[5], wB[5]);
        const float sA = __fadd_rn(hsum2(add2(a0, a1)), MAGIC);  // rne(dA)+M
        const float sC = __fadd_rn(hsum2(add2(c0, c1)), MAGIC);
        const float sB = __fadd_rn(hsum2(add2(e0, e1)), MAGIC);

        const float vAM = __fadd_rn(sA, i0);        // ii_r + hh_r + M
        const float vBM = __fadd_rn(sB, i1);
        const float qCr = __fmaf_rn(INV, sC, KC);   // (rne(dC)+cC)/128, exact

        // ---- fcnn FMA work in R8's filler position (no MIO ops here) ----
        const float qa = __fadd_rn(fmaxf(vAM, MAGIC), -MAGIC);
        const float qb = __fadd_rn(fmaxf(vBM, MAGIC), -MAGIC);
        const float qc = fmaxf(qCr, 0.0f);
        const float pa = __fmaf_rn(qa, w2a,
                         __fmaf_rn(qb, w2b, __fmul_rn(qc, w2cS)));

        // ---- gates (fused round-in-FMA), hM-form tail (R8 exact) ----
        const float rtM = fminf(fmaxf(__fmaf_rn(0.25f, vAM, K64), MAGIC), MP);
        const float ztM = fminf(fmaxf(__fmaf_rn(0.25f, vBM, K64), MAGIC), MP);
        const float rt  = __fadd_rn(rtM, -MAGIC);
        const float ztI = __fmul_rn(__fadd_rn(ztM, -MAGIC), INV);  // zt/128
        const float ntM = fminf(fmaxf(__fmaf_rn(rt, qCr, i2M), MM), MP);
        const float d   = __fadd_rn(hM_own, -ntM);   // h - nt, exact
        const float hnM = __fmaf_rn(ztI, d, ntM);    // exact single rounding
        const float hn  = __fadd_rn(hnM, -MAGIC);
        hM_own = hnM;

        // ---- broadcast h_t: STS own slot, LDS packed pairs (queue head) ----
        asm volatile("st.shared.b32 [%0], %1;" :: "r"(hst), "f"(hn) : "memory");
        asm volatile("ld.shared.v2.u64 {%0,%1}, [%2];"
                     : "=l"(hp[0]), "=l"(hp[1]) : "r"(hba) : "memory");
        asm volatile("ld.shared.v2.u64 {%0,%1}, [%2];"
                     : "=l"(hp[2]), "=l"(hp[3]) : "r"(hba + 16u) : "memory");
        asm volatile("ld.shared.v2.u64 {%0,%1}, [%2];"
                     : "=l"(hp[4]), "=l"(hp[5]) : "r"(hba + 32u) : "memory");

        // ---- fcnn MIO ops LAST (drain in LDS shadow; output for t-1) ----
        float ps = pa + __shfl_xor_sync(0xffffffffu, pa, 1);
        if (r == 12 && (unsigned)(t - 1) < 512u)
            op[t * BB] = __fmul_rn(
                __fadd_rn(__fadd_rn(ps, MAGIC), b2sM), INV);
    }
}

// ---------------------------------------------------------------------------
extern "C" void kernel_launch(void* const* d_in, const int* in_sizes, int n_in,
                              void* d_out, int out_size) {
    const float* input = (const float*)d_in[0];
    const float* wih   = (const float*)d_in[1];
    const float* whh   = (const float*)d_in[2];
    const float* bih   = (const float*)d_in[3];
    const float* bhh   = (const float*)d_in[4];
    const float* w1    = (const float*)d_in[5];
    const float* b1    = (const float*)d_in[6];
    const float* w2    = (const float*)d_in[7];
    const float* b2    = (const float*)d_in[8];
    float* out = (float*)d_out;

    gru_kernel<<<BB / 8, 128>>>(input, wih, whh, bih, bhh,
                                w1, b1, w2, b2, out);
}

// round 15
// speedup vs baseline: 1.0090x; 1.0090x over previous
#include <cuda_runtime.h>
#include <cuda_bf16.h>

// QuantizedGRU: T=512, B=1024, H=12, Q7 fixed point (scale 128).
// Round 15 = Round 8 skeleton (best, 48.1us: gates -> STS/LDS -> fcnn-last)
// with all three gates rewritten via EXACT sat-fma algebra:
//   r: sR = sat(v/512 + 1/2)          (pre-sat value exact, no rounding)
//      rt = fma(sR,128,M) - M         (single quantize round)
//   z: sZ = sat(v/512 + 1/2); ztI = (sZ + 98304) - 98304   (= zt/128)
//   n: v_n = ii + rt*hh is EXACT in fp32 (numerator <= 2^22), so
//      sN = sat(fma(rt, qCrH, i2h))   (qCrH = hh/256, i2h = (ii+128)/256)
//      ntM = fma(sN, 256, MAGIC-128)  (single quantize round, clip via sat)
// Path vAM->hnM: 36 -> 28 cyc. All other code identical to R8.
// Entire computation bit-exact vs reference (every rounding a verified
// single-rounding with preserved ties-to-even parity).

#define TT  512
#define BB  1024
#define INV 0.0078125f
#define MAGIC 12582912.0f            /* 1.5 * 2^23 */
#define C7   98304.0f                /* 1.5 * 2^16: ulp = 1/128 */
#define XROW 516                     /* padded x row: 512 + 4 OOB slots */

typedef unsigned long long u64;

__device__ __forceinline__ float rne(float v) {
    return __fadd_rn(__fadd_rn(v, MAGIC), -MAGIC);
}
__device__ __forceinline__ float rneq(float v) {
    return fminf(fmaxf(rne(v), -32768.0f), 32767.0f);
}
__device__ __forceinline__ float qs(float v) {   // quantized weight, scaled
    return rneq(__fmul_rn(v, 128.0f));
}
__device__ __forceinline__ float qr(float v) {   // quantized weight, real
    return __fmul_rn(qs(v), INV);
}
__device__ __forceinline__ float satfma(float a, float b, float c) {
    float r;
    asm("fma.rn.sat.f32 %0, %1, %2, %3;" : "=f"(r) : "f"(a), "f"(b), "f"(c));
    return r;
}
__device__ __forceinline__ u64 pk2(float lo, float hi) {
    u64 r;
    asm("mov.b64 %0, {%1, %2};" : "=l"(r) : "f"(lo), "f"(hi));
    return r;
}
__device__ __forceinline__ void fma2(u64& d, u64 a, u64 b) {
    asm("fma.rn.f32x2 %0, %1, %2, %0;" : "+l"(d) : "l"(a), "l"(b));
}
__device__ __forceinline__ u64 add2(u64 a, u64 b) {
    u64 r;
    asm("add.rn.f32x2 %0, %1, %2;" : "=l"(r) : "l"(a), "l"(b));
    return r;
}
__device__ __forceinline__ u64 mul2(u64 a, u64 b) {
    u64 r;
    asm("mul.rn.f32x2 %0, %1, %2;" : "=l"(r) : "l"(a), "l"(b));
    return r;
}
__device__ __forceinline__ void unpk2(float& lo, float& hi, u64 v) {
    asm("mov.b64 {%0, %1}, %2;" : "=f"(lo), "=f"(hi) : "l"(v));
}
__device__ __forceinline__ float hsum2(u64 v) {
    float lo, hi;
    unpk2(lo, hi, v);
    return __fadd_rn(lo, hi);
}
__device__ __forceinline__ unsigned smem_u32(const void* p) {
    unsigned a;
    asm("{ .reg .u64 t; cvta.to.shared.u64 t, %1; cvt.u32.u64 %0, t; }"
        : "=r"(a) : "l"(p));
    return a;
}

// ---------------------------------------------------------------------------
// 128 blocks x 128 threads: 8 batches/block, 16 threads/batch.
// lanes 0-11: gate triple r (W_hh rows r, r+12, r+24)
// lanes 12,13: FCNN rows (W1 rows 0-2 / 3-5), output pipelined 1 step behind
// lanes 14,15: zero weights (same instruction stream)
// ---------------------------------------------------------------------------
__global__ void __launch_bounds__(128, 1) gru_kernel(
        const float* __restrict__ x,
        const float* __restrict__ wih_raw, const float* __restrict__ whh_raw,
        const float* __restrict__ bih_raw, const float* __restrict__ bhh_raw,
        const float* __restrict__ w1_raw,  const float* __restrict__ b1_raw,
        const float* __restrict__ w2_raw,  const float* __restrict__ b2_raw,
        float* __restrict__ out) {
    __shared__ __align__(16) float xs[8 * XROW];       // [batch][t], padded
    __shared__ __align__(16) float hbuf[8 * 16];       // h broadcast rows

    const int tid = threadIdx.x;
    const int r   = tid & 15;
    const int bb  = tid >> 4;
    const int b0  = blockIdx.x << 3;
    const int b   = b0 + bb;

    // stage x transposed: xs[bj][t] = x[t][b0+bj]; zero the 4 pad slots
    for (int i = tid; i < TT * 8; i += 128) {
        const int t  = i >> 3;
        const int bj = i & 7;
        xs[bj * XROW + t] = x[t * BB + b0 + bj];
    }
    if (tid < 32) xs[(tid >> 2) * XROW + TT + (tid & 3)] = 0.0f;

    // ---- per-lane constants ----
    u64 wA[6], wB[6], wC[6];
    u64 ws01 = 0, cb01M = pk2(-MAGIC, -MAGIC);
    float ws2 = 0.f, cb2 = 0.f;
    const float INV15 = 3.0517578125e-05f;             // 2^-15
    float KCH = __fmul_rn(-MAGIC, INV15);              // (cC - M) * 2^-15
    float w2a = 0.f, w2b = 0.f, w2c256 = 0.f;          // w2c scaled*256
#pragma unroll
    for (int k = 0; k < 6; ++k) { wA[k] = 0; wB[k] = 0; wC[k] = 0; }

    if (r < 12) {
        const float* pA = whh_raw + r * 12;            // r-gate row
        const float* pB = whh_raw + (r + 12) * 12;     // z-gate row
        const float* pC = whh_raw + (r + 24) * 12;     // n-gate row
#pragma unroll
        for (int k = 0; k < 6; ++k) {
            wA[k] = pk2(qr(pA[2 * k]), qr(pA[2 * k + 1]));
            wB[k] = pk2(qr(pB[2 * k]), qr(pB[2 * k + 1]));
            wC[k] = pk2(qr(pC[2 * k]), qr(pC[2 * k + 1]));
        }
        ws01  = pk2(qs(wih_raw[r]), qs(wih_raw[r + 12]));
        cb01M = pk2((qs(bih_raw[r])      + qs(bhh_raw[r]))      - MAGIC,
                    (qs(bih_raw[r + 12]) + qs(bhh_raw[r + 12])) - MAGIC);
        ws2 = qs(wih_raw[r + 24]);
        cb2 = qs(bih_raw[r + 24]);
        KCH = __fmul_rn(qs(bhh_raw[r + 24]) - MAGIC, INV15);
    } else if (r < 14) {
        const int r0 = (r - 12) * 3;
#pragma unroll
        for (int j = 0; j < 3; ++j) {
            const float* p = w1_raw + (r0 + j) * 12;
            u64* w = (j == 0) ? wA : ((j == 1) ? wB : wC);
#pragma unroll
            for (int k = 0; k < 6; ++k)
                w[k] = pk2(qr(p[2 * k]), qr(p[2 * k + 1]));
        }
        cb01M = pk2(qs(b1_raw[r0 + 0]) - MAGIC,
                    qs(b1_raw[r0 + 1]) - MAGIC);
        KCH   = __fmul_rn(qs(b1_raw[r0 + 2]) - MAGIC, INV15);
        w2a   = qr(w2_raw[r0 + 0]);
        w2b   = qr(w2_raw[r0 + 1]);
        w2c256 = __fmul_rn(qs(w2_raw[r0 + 2]), 256.0f); // exact scale
    }
    const float b2sM = qs(b2_raw[0]) - MAGIC;
    const float c512 = 0.001953125f;            // 1/512, exact
    const float KA   = -24575.5f;               // 0.5 - MAGIC/512, exact
    const float c256 = 0.00390625f;             // 1/256
    const float K49  = 49151.5f;                // (MAGIC-128)/256, exact
    const float MM   = MAGIC - 128.0f;
    const u64   M2   = pk2(MAGIC, MAGIC);

    __syncthreads();

    u64 hp[6];
#pragma unroll
    for (int k = 0; k < 6; ++k) hp[k] = 0;
    float hM_own = MAGIC;                       // h + MAGIC, h0 = 0
    float* op    = out + b - BB;                // output for step t-1

    const unsigned xsa = smem_u32(xs + bb * XROW);
    const unsigned hba = smem_u32(hbuf) + (bb << 6);
    const unsigned hst = hba + (r << 2);

    float4 xq = make_float4(0.f, 0.f, 0.f, 0.f);

#pragma unroll 4
    for (int t = 0; t <= TT; ++t) {
        if ((t & 3) == 0) {
            asm volatile("ld.shared.v4.f32 {%0,%1,%2,%3}, [%4];"
                : "=f"(xq.x), "=f"(xq.y), "=f"(xq.z), "=f"(xq.w)
                : "r"(xsa + (unsigned)t * 4u));
        }
        const float xcur = ((t & 3) == 0) ? xq.x :
                           ((t & 3) == 1) ? xq.y :
                           ((t & 3) == 2) ? xq.z : xq.w;

        // ii precompute (off critical path); packed for r/z, scalar for n.
        const u64 i01 = add2(add2(mul2(pk2(xcur, xcur), ws01), M2), cb01M);
        float i0, i1;
        unpk2(i0, i1, i01);                     // true ints
        const float i2M = __fadd_rn(__fadd_rn(__fmul_rn(xcur, ws2), MAGIC), cb2);
        // i2h = (ii_n + 128)/256 = v-addend for the n-gate sat form (exact)
        const float i2h = __fmaf_rn(i2M, c256, -K49);

        // ---- packed dots with h_{t-1} (two 3-deep chains per row) ----
        u64 a0 = 0, a1 = 0, c0 = 0, c1 = 0, e0 = 0, e1 = 0;
        fma2(a0, hp[0], wA[0]); fma2(a0, hp[1], wA[1]); fma2(a0, hp[2], wA[2]);
        fma2(a1, hp[3], wA[3]); fma2(a1, hp[4], wA[4]); fma2(a1, hp[5], wA[5]);
        fma2(c0, hp[0], wC[0]); fma2(c0, hp[1], wC[1]); fma2(c0, hp[2], wC[2]);
        fma2(c1, hp[3], wC[3]); fma2(c1, hp[4], wC[4]); fma2(c1, hp[5], wC[5]);
        fma2(e0, hp[0], wB[0]); fma2(e0, hp[1], wB[1]); fma2(e0, hp[2], wB[2]);
        fma2(e1, hp[3], wB[3]); fma2(e1, hp[4], wB[4]); fma2(e1, hp[5], wB[5]);
        const float sA = __fadd_rn(hsum2(add2(a0, a1)), MAGIC);  // rne(dA)+M
        const float sC = __fadd_rn(hsum2(add2(c0, c1)), MAGIC);
        const float sB = __fadd_rn(hsum2(add2(e0, e1)), MAGIC);

        const float vAM  = __fadd_rn(sA, i0);        // ii_r + hh_r + M
        const float vBM  = __fadd_rn(sB, i1);
        const float qCrH = __fmaf_rn(INV15, sC, KCH);  // hh_n/256, exact

        // ---- gates: exact sat-fma forms, hM tail ----
        const float sR  = satfma(vAM, c512, KA);     // clip(v/512+.5,0,1), exact
        const float sZ  = satfma(vBM, c512, KA);
        const float rtQ = __fmaf_rn(sR, 128.0f, MAGIC);  // rne(128 sR)+M
        const float rt  = __fadd_rn(rtQ, -MAGIC);        // rt scaled int
        const float ztI = __fadd_rn(__fadd_rn(sZ, C7), -C7);  // zt/128
        const float sN  = satfma(rt, qCrH, i2h);     // clip((v_n+1)/2,0,1), exact
        const float ntM = __fmaf_rn(sN, 256.0f, MM); // rne(128 v_n)+M
        const float d   = __fadd_rn(hM_own, -ntM);   // h - nt, exact
        const float hnM = __fmaf_rn(ztI, d, ntM);    // exact single rounding
        const float hn  = __fadd_rn(hnM, -MAGIC);
        hM_own = hnM;

        // ---- broadcast h_t: STS own slot, LDS packed pairs (R8 order) ----
        asm volatile("st.shared.b32 [%0], %1;" :: "r"(hst), "f"(hn) : "memory");
        asm volatile("ld.shared.v2.u64 {%0,%1}, [%2];"
                     : "=l"(hp[0]), "=l"(hp[1]) : "r"(hba) : "memory");
        asm volatile("ld.shared.v2.u64 {%0,%1}, [%2];"
                     : "=l"(hp[2]), "=l"(hp[3]) : "r"(hba + 16u) : "memory");
        asm volatile("ld.shared.v2.u64 {%0,%1}, [%2];"
                     : "=l"(hp[4]), "=l"(hp[5]) : "r"(hba + 32u) : "memory");

        // ---- fcnn epilogue LAST (R8 placement; output for step t-1) ----
        const float qa = __fadd_rn(fmaxf(vAM, MAGIC), -MAGIC);
        const float qb = __fadd_rn(fmaxf(vBM, MAGIC), -MAGIC);
        const float qc = fmaxf(qCrH, 0.0f);          // q1_real/256
        float pa = __fmaf_rn(qa, w2a,
                   __fmaf_rn(qb, w2b, __fmul_rn(qc, w2c256)));
        pa += __shfl_xor_sync(0xffffffffu, pa, 1);
        if (r == 12 && (unsigned)(t - 1) < 512u)
            op[t * BB] = __fmul_rn(
                __fadd_rn(__fadd_rn(pa, MAGIC), b2sM), INV);
    }
}

// ---------------------------------------------------------------------------
extern "C" void kernel_launch(void* const* d_in, const int* in_sizes, int n_in,
                              void* d_out, int out_size) {
    const float* input = (const float*)d_in[0];
    const float* wih   = (const float*)d_in[1];
    const float* whh   = (const float*)d_in[2];
    const float* bih   = (const float*)d_in[3];
    const float* bhh   = (const float*)d_in[4];
    const float* w1    = (const float*)d_in[5];
    const float* b1    = (const float*)d_in[6];
    const float* w2    = (const float*)d_in[7];
    const float* b2    = (const float*)d_in[8];
    float* out = (float*)d_out;

    gru_kernel<<<BB / 8, 128>>>(input, wih, whh, bih, bhh,
                                w1, b1, w2, b2, out);
}

// round 16
// speedup vs baseline: 1.0482x; 1.0388x over previous
#include <cuda_runtime.h>
#include <cuda_bf16.h>

// QuantizedGRU: T=512, B=1024, H=12, Q7 fixed point (scale 128).
// FINAL = Round 8 verbatim (best measured: 48.1us, rel_err 0.0).
// Architecture: 128 blocks x 128 threads = 512 warps = exactly one warp
// per SMSP chip-wide (proven optimal: TLP-2 and ILP-2 both regressed).
// Per step: packed f32x2 dots (weights in registers), fused round-in-FMA
// quantizes (magic-constant single-roundings, ties-to-even preserved),
// hM-form update tail, h broadcast via asm-pinned STS + 3x ld.shared.v2.u64.
// All arithmetic in the exact x128 scaled-integer fp32 domain (bit-exact).

#define TT  512
#define BB  1024
#define INV 0.0078125f
#define MAGIC 12582912.0f            /* 1.5 * 2^23 */
#define XROW 516                     /* padded x row: 512 + 4 OOB slots */

typedef unsigned long long u64;

__device__ __forceinline__ float rne(float v) {
    return __fadd_rn(__fadd_rn(v, MAGIC), -MAGIC);
}
__device__ __forceinline__ float rneq(float v) {
    return fminf(fmaxf(rne(v), -32768.0f), 32767.0f);
}
__device__ __forceinline__ float qs(float v) {   // quantized weight, scaled
    return rneq(__fmul_rn(v, 128.0f));
}
__device__ __forceinline__ float qr(float v) {   // quantized weight, real
    return __fmul_rn(qs(v), INV);
}
__device__ __forceinline__ u64 pk2(float lo, float hi) {
    u64 r;
    asm("mov.b64 %0, {%1, %2};" : "=l"(r) : "f"(lo), "f"(hi));
    return r;
}
__device__ __forceinline__ void fma2(u64& d, u64 a, u64 b) {
    asm("fma.rn.f32x2 %0, %1, %2, %0;" : "+l"(d) : "l"(a), "l"(b));
}
__device__ __forceinline__ u64 add2(u64 a, u64 b) {
    u64 r;
    asm("add.rn.f32x2 %0, %1, %2;" : "=l"(r) : "l"(a), "l"(b));
    return r;
}
__device__ __forceinline__ u64 mul2(u64 a, u64 b) {
    u64 r;
    asm("mul.rn.f32x2 %0, %1, %2;" : "=l"(r) : "l"(a), "l"(b));
    return r;
}
__device__ __forceinline__ void unpk2(float& lo, float& hi, u64 v) {
    asm("mov.b64 {%0, %1}, %2;" : "=f"(lo), "=f"(hi) : "l"(v));
}
__device__ __forceinline__ float hsum2(u64 v) {
    float lo, hi;
    unpk2(lo, hi, v);
    return __fadd_rn(lo, hi);
}
__device__ __forceinline__ unsigned smem_u32(const void* p) {
    unsigned a;
    asm("{ .reg .u64 t; cvta.to.shared.u64 t, %1; cvt.u32.u64 %0, t; }"
        : "=r"(a) : "l"(p));
    return a;
}

// ---------------------------------------------------------------------------
// 128 blocks x 128 threads: 8 batches/block, 16 threads/batch.
// lanes 0-11: gate triple r (W_hh rows r, r+12, r+24)
// lanes 12,13: FCNN rows (W1 rows 0-2 / 3-5), output pipelined 1 step behind
// lanes 14,15: zero weights (same instruction stream)
// ---------------------------------------------------------------------------
__global__ void __launch_bounds__(128, 1) gru_kernel(
        const float* __restrict__ x,
        const float* __restrict__ wih_raw, const float* __restrict__ whh_raw,
        const float* __restrict__ bih_raw, const float* __restrict__ bhh_raw,
        const float* __restrict__ w1_raw,  const float* __restrict__ b1_raw,
        const float* __restrict__ w2_raw,  const float* __restrict__ b2_raw,
        float* __restrict__ out) {
    __shared__ __align__(16) float xs[8 * XROW];       // [batch][t], padded
    __shared__ __align__(16) float hbuf[8 * 16];       // h broadcast rows

    const int tid = threadIdx.x;
    const int r   = tid & 15;
    const int bb  = tid >> 4;
    const int b0  = blockIdx.x << 3;
    const int b   = b0 + bb;

    // stage x transposed: xs[bj][t] = x[t][b0+bj]; zero the 4 pad slots
    for (int i = tid; i < TT * 8; i += 128) {
        const int t  = i >> 3;
        const int bj = i & 7;
        xs[bj * XROW + t] = x[t * BB + b0 + bj];
    }
    if (tid < 32) xs[(tid >> 2) * XROW + TT + (tid & 3)] = 0.0f;

    // ---- per-lane constants ----
    u64 wA[6], wB[6], wC[6];
    u64 ws01 = 0, cb01M = pk2(-MAGIC, -MAGIC);
    float ws2 = 0.f, cb2 = 0.f;
    float KC = __fmul_rn(-MAGIC, INV);
    float w2a = 0.f, w2b = 0.f, w2cS = 0.f;            // w2cS: SCALED weight
#pragma unroll
    for (int k = 0; k < 6; ++k) { wA[k] = 0; wB[k] = 0; wC[k] = 0; }

    if (r < 12) {
        const float* pA = whh_raw + r * 12;            // r-gate row
        const float* pB = whh_raw + (r + 12) * 12;     // z-gate row
        const float* pC = whh_raw + (r + 24) * 12;     // n-gate row
#pragma unroll
        for (int k = 0; k < 6; ++k) {
            wA[k] = pk2(qr(pA[2 * k]), qr(pA[2 * k + 1]));
            wB[k] = pk2(qr(pB[2 * k]), qr(pB[2 * k + 1]));
            wC[k] = pk2(qr(pC[2 * k]), qr(pC[2 * k + 1]));
        }
        ws01  = pk2(qs(wih_raw[r]), qs(wih_raw[r + 12]));
        cb01M = pk2((qs(bih_raw[r])      + qs(bhh_raw[r]))      - MAGIC,
                    (qs(bih_raw[r + 12]) + qs(bhh_raw[r + 12])) - MAGIC);
        ws2 = qs(wih_raw[r + 24]);
        cb2 = qs(bih_raw[r + 24]);
        KC  = __fmul_rn(qs(bhh_raw[r + 24]) - MAGIC, INV);
    } else if (r < 14) {
        const int r0 = (r - 12) * 3;
#pragma unroll
        for (int j = 0; j < 3; ++j) {
            const float* p = w1_raw + (r0 + j) * 12;
            u64* w = (j == 0) ? wA : ((j == 1) ? wB : wC);
#pragma unroll
            for (int k = 0; k < 6; ++k)
                w[k] = pk2(qr(p[2 * k]), qr(p[2 * k + 1]));
        }
        cb01M = pk2(qs(b1_raw[r0 + 0]) - MAGIC,
                    qs(b1_raw[r0 + 1]) - MAGIC);
        KC   = __fmul_rn(qs(b1_raw[r0 + 2]) - MAGIC, INV);
        w2a  = qr(w2_raw[r0 + 0]);
        w2b  = qr(w2_raw[r0 + 1]);
        w2cS = qs(w2_raw[r0 + 2]);   // scaled, since qCr is real-domain
    }
    const float b2sM = qs(b2_raw[0]) - MAGIC;
    const float K64  = 64.0f + 0.75f * MAGIC;   // exact
    const float MP   = MAGIC + 128.0f;
    const float MM   = MAGIC - 128.0f;
    const u64   M2   = pk2(MAGIC, MAGIC);

    __syncthreads();

    u64 hp[6];
#pragma unroll
    for (int k = 0; k < 6; ++k) hp[k] = 0;
    float hM_own = MAGIC;                       // h + MAGIC, h0 = 0
    float* op    = out + b - BB;                // output for step t-1

    const unsigned xsa = smem_u32(xs + bb * XROW);
    const unsigned hba = smem_u32(hbuf) + (bb << 6);
    const unsigned hst = hba + (r << 2);

    float4 xq = make_float4(0.f, 0.f, 0.f, 0.f);

#pragma unroll 4
    for (int t = 0; t < 516; ++t) {
        if ((t & 3) == 0) {
            asm volatile("ld.shared.v4.f32 {%0,%1,%2,%3}, [%4];"
                : "=f"(xq.x), "=f"(xq.y), "=f"(xq.z), "=f"(xq.w)
                : "r"(xsa + (unsigned)t * 4u));
        }
        const float xcur = ((t & 3) == 0) ? xq.x :
                           ((t & 3) == 1) ? xq.y :
                           ((t & 3) == 2) ? xq.z : xq.w;

        // ii precompute (off critical path); packed for r/z, scalar for n.
        const u64 i01 = add2(add2(mul2(pk2(xcur, xcur), ws01), M2), cb01M);
        float i0, i1;
        unpk2(i0, i1, i01);                     // true ints
        const float i2M = __fadd_rn(__fadd_rn(__fmul_rn(xcur, ws2), MAGIC), cb2);

        // ---- packed dots with h_{t-1} (two 3-deep chains per row) ----
        u64 a0 = 0, a1 = 0, c0 = 0, c1 = 0, e0 = 0, e1 = 0;
        fma2(a0, hp[0], wA[0]); fma2(a0, hp[1], wA[1]); fma2(a0, hp[2], wA[2]);
        fma2(a1, hp[3], wA[3]); fma2(a1, hp[4], wA[4]); fma2(a1, hp[5], wA[5]);
        fma2(c0, hp[0], wC[0]); fma2(c0, hp[1], wC[1]); fma2(c0, hp[2], wC[2]);
        fma2(c1, hp[3], wC[3]); fma2(c1, hp[4], wC[4]); fma2(c1, hp[5], wC[5]);
        fma2(e0, hp[0], wB[0]); fma2(e0, hp[1], wB[1]); fma2(e0, hp[2], wB[2]);
        fma2(e1, hp[3], wB[3]); fma2(e1, hp[4], wB[4]); fma2(e1, hp[5], wB[5]);
        const float sA = __fadd_rn(hsum2(add2(a0, a1)), MAGIC);  // rne(dA)+M
        const float sC = __fadd_rn(hsum2(add2(c0, c1)), MAGIC);
        const float sB = __fadd_rn(hsum2(add2(e0, e1)), MAGIC);

        const float vAM = __fadd_rn(sA, i0);        // ii_r + hh_r + M
        const float vBM = __fadd_rn(sB, i1);
        const float qCr = __fmaf_rn(INV, sC, KC);   // (rne(dC)+cC)/128, exact

        // ---- fcnn epilogue (lanes 12,13): output for step t-1 ----
        const float qa = __fadd_rn(fmaxf(vAM, MAGIC), -MAGIC);
        const float qb = __fadd_rn(fmaxf(vBM, MAGIC), -MAGIC);
        const float qc = fmaxf(qCr, 0.0f);
        float pa = __fmaf_rn(qa, w2a,
                   __fmaf_rn(qb, w2b, __fmul_rn(qc, w2cS)));
        pa += __shfl_xor_sync(0xffffffffu, pa, 1);
        if (r == 12 && (unsigned)(t - 1) < 512u)
            op[t * BB] = __fmul_rn(
                __fadd_rn(__fadd_rn(pa, MAGIC), b2sM), INV);

        // ---- gates (fused round-in-FMA), hM-form tail ----
        const float rtM = fminf(fmaxf(__fmaf_rn(0.25f, vAM, K64), MAGIC), MP);
        const float ztM = fminf(fmaxf(__fmaf_rn(0.25f, vBM, K64), MAGIC), MP);
        const float rt  = __fadd_rn(rtM, -MAGIC);
        const float ztI = __fmul_rn(__fadd_rn(ztM, -MAGIC), INV);  // zt/128
        const float ntM = fminf(fmaxf(__fmaf_rn(rt, qCr, i2M), MM), MP);
        const float d   = __fadd_rn(hM_own, -ntM);   // h - nt, exact
        const float hnM = __fmaf_rn(ztI, d, ntM);    // exact single rounding
        const float hn  = __fadd_rn(hnM, -MAGIC);
        hM_own = hnM;

        // ---- broadcast h_t: STS own slot, LDS packed pairs ----
        asm volatile("st.shared.b32 [%0], %1;" :: "r"(hst), "f"(hn) : "memory");
        asm volatile("ld.shared.v2.u64 {%0,%1}, [%2];"
                     : "=l"(hp[0]), "=l"(hp[1]) : "r"(hba) : "memory");
        asm volatile("ld.shared.v2.u64 {%0,%1}, [%2];"
                     : "=l"(hp[2]), "=l"(hp[3]) : "r"(hba + 16u) : "memory");
        asm volatile("ld.shared.v2.u64 {%0,%1}, [%2];"
                     : "=l"(hp[4]), "=l"(hp[5]) : "r"(hba + 32u) : "memory");
    }
}

// ---------------------------------------------------------------------------
extern "C" void kernel_launch(void* const* d_in, const int* in_sizes, int n_in,
                              void* d_out, int out_size) {
    const float* input = (const float*)d_in[0];
    const float* wih   = (const float*)d_in[1];
    const float* whh   = (const float*)d_in[2];
    const float* bih   = (const float*)d_in[3];
    const float* bhh   = (const float*)d_in[4];
    const float* w1    = (const float*)d_in[5];
    const float* b1    = (const float*)d_in[6];
    const float* w2    = (const float*)d_in[7];
    const float* b2    = (const float*)d_in[8];
    float* out = (float*)d_out;

    gru_kernel<<<BB / 8, 128>>>(input, wih, whh, bih, bhh,
                                w1, b1, w2, b2, out);
}